// round 14
// baseline (speedup 1.0000x reference)
#include <cuda_runtime.h>
#include <cuda_fp16.h>
#include <math.h>
#include <stdint.h>

// Problem dims
#define Tn 128
#define Bn 512
#define Dn 1024
#define Hn 128
#define G4 512   // 4*H
#define BH (Bn*Hn)

// -------- scratch (device globals: no allocations allowed) --------
__device__ float  g_pre[(size_t)Tn * Bn * G4];  // [t][b][4H]
__device__ __half g_Ah[(size_t)Bn * Tn * Dn];   // feats fp16
__device__ __half g_Wh[G4 * Dn];                // Wih1 fp16
__device__ __half g_h1h[2 * BH];                // fp16 h1 ping-pong
__device__ __half g_h2h[2 * BH];                // fp16 h2 ping-pong
__device__ __align__(32) unsigned g_stamp[16 * 8];  // per-group arrival stamps

// ============================================================================
// helpers
// ============================================================================
__device__ __forceinline__ uint32_t smem_u32(const void* p) {
    uint32_t a;
    asm("{ .reg .u64 t; cvta.to.shared.u64 t, %1; cvt.u32.u64 %0, t; }"
        : "=r"(a) : "l"(p));
    return a;
}

__device__ __forceinline__ void ldsm4(uint32_t* r, uint32_t addr) {
    asm volatile("ldmatrix.sync.aligned.m8n8.x4.shared.b16 {%0,%1,%2,%3}, [%4];"
                 : "=r"(r[0]), "=r"(r[1]), "=r"(r[2]), "=r"(r[3]) : "r"(addr));
}

__device__ __forceinline__ void mma16816h(float* d, const uint32_t* a, const uint32_t* b) {
    asm volatile(
        "mma.sync.aligned.m16n8k16.row.col.f32.f16.f16.f32 "
        "{%0,%1,%2,%3}, {%4,%5,%6,%7}, {%8,%9}, {%0,%1,%2,%3};"
        : "+f"(d[0]), "+f"(d[1]), "+f"(d[2]), "+f"(d[3])
        : "r"(a[0]), "r"(a[1]), "r"(a[2]), "r"(a[3]), "r"(b[0]), "r"(b[1]));
}

__device__ __forceinline__ uint4 pack8h(float4 v0, float4 v1) {
    __half2 h0 = __floats2half2_rn(v0.x, v0.y);
    __half2 h1 = __floats2half2_rn(v0.z, v0.w);
    __half2 h2 = __floats2half2_rn(v1.x, v1.y);
    __half2 h3 = __floats2half2_rn(v1.z, v1.w);
    return make_uint4(*(uint32_t*)&h0, *(uint32_t*)&h1,
                      *(uint32_t*)&h2, *(uint32_t*)&h3);
}

#define CP16(dst, src) \
    asm volatile("cp.async.cg.shared.global [%0], [%1], 16;" \
                 :: "r"(dst), "l"(src) : "memory")
#define CP_COMMIT() asm volatile("cp.async.commit_group;" ::: "memory")
#define CP_WAIT1()  asm volatile("cp.async.wait_group 1;" ::: "memory")
#define CP_WAIT0()  asm volatile("cp.async.wait_group 0;" ::: "memory")

// -------- fp32 -> fp16 bulk convert --------
__global__ void __launch_bounds__(256) cvt_fp16_kernel(
    const float* __restrict__ s, __half* __restrict__ d, int n8)
{
    int i = blockIdx.x * blockDim.x + threadIdx.x;
    int stride = gridDim.x * blockDim.x;
    for (; i < n8; i += stride) {
        const float4* sp = (const float4*)s + 2 * (size_t)i;
        *(uint4*)((char*)d + 16 * (size_t)i) = pack8h(sp[0], sp[1]);
    }
}

// ============================================================================
// pre-projection GEMM (unchanged, validated)
// ============================================================================
#define NSTG 3

__global__ void __launch_bounds__(256, 2) gemm_pre_mma(
    const __half* __restrict__ Ah,   // [65536][1024]
    const __half* __restrict__ Wh,   // [512][1024]
    const float* __restrict__ b1,    // [512]
    const float* __restrict__ b2,    // [512]
    float* __restrict__ out)         // [T][B][512]
{
    __shared__ __align__(128) char smbuf[NSTG * 16384];
    __shared__ float bias_s[128];

    const int tid  = threadIdx.x;
    const int lane = tid & 31;
    const int wid  = tid >> 5;
    const int n0 = blockIdx.x * 128;
    const int m0 = blockIdx.y * 128;
    const uint32_t sb = smem_u32(smbuf);

    if (tid < 128) bias_s[tid] = b1[n0 + tid] + b2[n0 + tid];

    const int r   = tid >> 1;
    const int u0  = (tid & 1) * 2;
    const int ssw = (r >> 1) & 3;
    const uint32_t so0 = r * 64 + (((u0)     ^ ssw) << 4);
    const uint32_t so1 = r * 64 + (((u0 + 1) ^ ssw) << 4);

    const __half* arow = Ah + (size_t)(m0 + r) * Dn;
    const __half* brow = Wh + (size_t)(n0 + r) * Dn;

    const int m0w = (wid >> 1) * 32;
    const int n0w = (wid & 1) * 64;

    const int rowA = m0w + (lane & 15);
    const int jA   = lane >> 4;
    const int swA  = (rowA >> 1) & 3;
    const uint32_t aA = sb + rowA * 64;
    const int rowB = n0w + (lane & 7) + ((lane >> 4) & 1) * 8;
    const int jB   = (lane >> 3) & 1;
    const int swB  = (rowB >> 1) & 3;
    const uint32_t aB = sb + 8192 + rowB * 64;

    float acc[2][8][4];
#pragma unroll
    for (int mi = 0; mi < 2; mi++)
#pragma unroll
        for (int ni = 0; ni < 8; ni++)
#pragma unroll
            for (int q = 0; q < 4; q++) acc[mi][ni][q] = 0.f;

    auto issue = [&](int kc, int stg) {
        const uint32_t d = sb + stg * 16384;
        const __half* as = arow + kc * 32 + u0 * 8;
        const __half* bs = brow + kc * 32 + u0 * 8;
        CP16(d + so0,        as);
        CP16(d + so1,        as + 8);
        CP16(d + 8192 + so0, bs);
        CP16(d + 8192 + so1, bs + 8);
        CP_COMMIT();
    };

    issue(0, 0);
    issue(1, 1);

#pragma unroll 1
    for (int kc = 0; kc < 32; kc++) {
        if (kc == 31) { CP_WAIT0(); } else { CP_WAIT1(); }
        __syncthreads();

        if (kc < 30) issue(kc + 2, (kc + 2) % NSTG);

        const uint32_t ba  = aA + (kc % NSTG) * 16384;
        const uint32_t bbb = aB + (kc % NSTG) * 16384;
#pragma unroll
        for (int kf = 0; kf < 2; kf++) {
            uint32_t Af[2][4], Bf[4][4];
            const int ja = (((2 * kf + jA) ^ swA) << 4);
            const int jb = (((2 * kf + jB) ^ swB) << 4);
            ldsm4(Af[0], ba + ja);
            ldsm4(Af[1], ba + 1024 + ja);
#pragma unroll
            for (int ng = 0; ng < 4; ng++)
                ldsm4(Bf[ng], bbb + ng * 1024 + jb);
#pragma unroll
            for (int mi = 0; mi < 2; mi++)
#pragma unroll
                for (int ni = 0; ni < 8; ni++)
                    mma16816h(acc[mi][ni], Af[mi], &Bf[ni >> 1][(ni & 1) * 2]);
        }
        __syncthreads();
    }

#pragma unroll
    for (int mi = 0; mi < 2; mi++) {
        int ma = m0 + m0w + mi * 16 + (lane >> 2);
        int mb = ma + 8;
        float* rowa = out + ((size_t)(ma & 127) * Bn + (ma >> 7)) * G4 + n0;
        float* rowb = out + ((size_t)(mb & 127) * Bn + (mb >> 7)) * G4 + n0;
#pragma unroll
        for (int ni = 0; ni < 8; ni++) {
            int nl = n0w + ni * 8 + (lane & 3) * 2;
            float bv0 = bias_s[nl], bv1 = bias_s[nl + 1];
            float2 v;
            v.x = acc[mi][ni][0] + bv0;
            v.y = acc[mi][ni][1] + bv1;
            *(float2*)(rowa + nl) = v;
            v.x = acc[mi][ni][2] + bv0;
            v.y = acc[mi][ni][3] + bv1;
            *(float2*)(rowb + nl) = v;
        }
    }
}

// ============================================================================
// persistent recurrence — r10 structure + stamp barrier + fused dual GEMM
// Grid: 128 CTAs = 16 batch-groups x 8 unit-CTAs (NO cluster launch).
// ============================================================================
__device__ __forceinline__ float sigf(float x) {
    return __fdividef(1.f, 1.f + __expf(-x));
}
__device__ __forceinline__ float tanhfast(float x) {
    return __fmaf_rn(2.f, __fdividef(1.f, 1.f + __expf(-2.f * x)), -1.f);
}

// SMEM byte offsets
#define ROF_W1   0          // Whh1 fp16 [64][128] swizzled, 16KB
#define ROF_WI2  16384
#define ROF_WH2  32768
#define ROF_HA   49152      // h1 tile [32][128] fp16 swizzled, 8KB
#define ROF_HB   57344      // h2 tile
#define ROF_G    65536      // gates fp32 [32][68]
#define ROF_PRE  74240      // pre fp32 [2][32][64]
#define ROF_C1   90624
#define ROF_C2   92672
#define ROF_B2   94720
#define R_SMEM   95040

#define GS 68   // G row stride (floats)

__global__ void __launch_bounds__(256, 1) lstm_persist(
    const float* __restrict__ pre,    // [T][B][512]
    const float* __restrict__ Whh1,   // [512][128]
    const float* __restrict__ Wih2,   // [512][128]
    const float* __restrict__ Whh2,   // [512][128]
    const float* __restrict__ bih2,   // [512]
    const float* __restrict__ bhh2,   // [512]
    float* __restrict__ h2out)        // [B][128] (d_out)
{
    extern __shared__ char sm[];
    const uint32_t sb = smem_u32(sm);
    const int tid  = threadIdx.x;
    const int lane = tid & 31;
    const int wid  = tid >> 5;
    const int bb   = blockIdx.x >> 3;   // 0..15 (barrier group)
    const int ub   = blockIdx.x & 7;    // 0..7

    float* Gf  = (float*)(sm + ROF_G);
    float* prs = (float*)(sm + ROF_PRE);
    float* c1s = (float*)(sm + ROF_C1);
    float* c2s = (float*)(sm + ROF_C2);
    float* b2s = (float*)(sm + ROF_B2);

    // stamp base: all 8 slots of the group are equal at launch boundaries
    const unsigned sbase = *(volatile unsigned*)&g_stamp[bb * 8 + ub];

    // ---- init: weights -> fp16 smem (swizzled), zero state ----
    for (int idx = tid; idx < 64 * 128; idx += 256) {
        int j = idx >> 7;
        int k = idx & 127;
        int gcol = ((j >> 4) << 7) + (ub << 4) + (j & 15);
        uint32_t ad = (uint32_t)(j * 256 + (((k >> 3) ^ (j & 7)) << 4) + (k & 7) * 2);
        *(__half*)(sm + ROF_W1  + ad) = __float2half(Whh1[(size_t)gcol * Hn + k]);
        *(__half*)(sm + ROF_WI2 + ad) = __float2half(Wih2[(size_t)gcol * Hn + k]);
        *(__half*)(sm + ROF_WH2 + ad) = __float2half(Whh2[(size_t)gcol * Hn + k]);
    }
    if (tid < 64) {
        int gcol = ((tid >> 4) << 7) + (ub << 4) + (tid & 15);
        b2s[tid] = bih2[gcol] + bhh2[gcol];
    }
    for (int i = tid; i < 512; i += 256) { c1s[i] = 0.f; c2s[i] = 0.f; }
    for (int i = tid; i < 2048; i += 256) ((uint32_t*)(sm + ROF_HA))[i] = 0;
    {
        int u = tid & 15;
        int bl = tid >> 4;
#pragma unroll
        for (int i = 0; i < 2; i++) {
            int row = bb * 32 + bl + i * 16;
            g_h1h[row * Hn + ub * 16 + u] = __float2half(0.f);
            g_h2h[row * Hn + ub * 16 + u] = __float2half(0.f);
        }
    }
    // prefetch pre[0] slice into pres buf 0
    {
#pragma unroll
        for (int i = 0; i < 2; i++) {
            int q = 2 * tid + i;
            int b = q >> 4, ch = q & 15;
            int gcol0 = ((ch >> 2) << 7) + (ub << 4) + (ch & 3) * 4;
            const float* src = pre + ((size_t)(bb * 32 + b)) * G4 + gcol0;
            CP16(sb + ROF_PRE + (b * 64 + ch * 4) * 4, src);
        }
        CP_COMMIT();
    }
    __syncthreads();   // init smem (weights, hA zeros) visible CTA-wide

    // ---- per-thread mma geometry (warp tile 16m x 16n; 2x4 warp grid) ----
    const int m_off = (wid >> 2) * 16;
    const int n_off = (wid & 3) * 16;
    const int rowA = m_off + (lane & 15);
    const uint32_t aoffA = rowA * 256;
    const int swA = rowA & 7;
    const int kuA0 = lane >> 4;
    const int rowB = n_off + (lane & 7) + ((lane >> 4) & 1) * 8;
    const uint32_t boffB = rowB * 256;
    const int swB = rowB & 7;
    const int kuB0 = (lane >> 3) & 1;

    const int u2 = tid & 15;
    const int bq = (tid >> 4) * 2;

    auto gemm_acc = [&](uint32_t hbase, uint32_t wbase, float acc[2][4]) {
#pragma unroll
        for (int ks = 0; ks < 8; ks++) {
            uint32_t Af[4], Bf[4];
            int kuA = 2 * ks + kuA0;
            int kuB = 2 * ks + kuB0;
            ldsm4(Af, sb + hbase + aoffA + (uint32_t)(((kuA ^ swA)) << 4));
            ldsm4(Bf, sb + wbase + boffB + (uint32_t)(((kuB ^ swB)) << 4));
            mma16816h(acc[0], Af, Bf);
            mma16816h(acc[1], Af, Bf + 2);
        }
    };
    // fused dual GEMM: acc += h1b@w1b^T + h2b@w2b^T  (4 ldsm + 4 mma per ks)
    auto gemm2_acc = [&](uint32_t h1b, uint32_t w1b, uint32_t h2b, uint32_t w2b,
                         float acc[2][4]) {
#pragma unroll
        for (int ks = 0; ks < 8; ks++) {
            uint32_t Af[4], Bf[4], Cf[4], Df[4];
            int kuA = 2 * ks + kuA0;
            int kuB = 2 * ks + kuB0;
            uint32_t oA = (uint32_t)(((kuA ^ swA)) << 4);
            uint32_t oB = (uint32_t)(((kuB ^ swB)) << 4);
            ldsm4(Af, sb + h1b + aoffA + oA);
            ldsm4(Bf, sb + w1b + boffB + oB);
            ldsm4(Cf, sb + h2b + aoffA + oA);
            ldsm4(Df, sb + w2b + boffB + oB);
            mma16816h(acc[0], Af, Bf);
            mma16816h(acc[1], Af, Bf + 2);
            mma16816h(acc[0], Cf, Df);
            mma16816h(acc[1], Cf, Df + 2);
        }
    };
    auto stage_G = [&](float acc[2][4]) {
        int r0 = m_off + (lane >> 2);
        int c0 = n_off + 2 * (lane & 3);
#pragma unroll
        for (int h = 0; h < 2; h++) {
            Gf[r0 * GS + c0 + 8 * h]           = acc[h][0];
            Gf[r0 * GS + c0 + 8 * h + 1]       = acc[h][1];
            Gf[(r0 + 8) * GS + c0 + 8 * h]     = acc[h][2];
            Gf[(r0 + 8) * GS + c0 + 8 * h + 1] = acc[h][3];
        }
    };

    // stamp barrier: release own slot, poll all 8, acquire
    auto group_barrier = [&](unsigned tgt) {
        __syncthreads();
        if (tid == 0) {
            __threadfence();
            asm volatile("st.release.gpu.global.u32 [%0], %1;"
                         :: "l"(&g_stamp[bb * 8 + ub]), "r"(tgt) : "memory");
            const unsigned* pp = &g_stamp[bb * 8];
            while (true) {
                unsigned a0, a1, a2, a3, b0, b1, b2, b3;
                asm volatile("ld.volatile.global.v4.u32 {%0,%1,%2,%3}, [%4];"
                             : "=r"(a0), "=r"(a1), "=r"(a2), "=r"(a3) : "l"(pp));
                asm volatile("ld.volatile.global.v4.u32 {%0,%1,%2,%3}, [%4];"
                             : "=r"(b0), "=r"(b1), "=r"(b2), "=r"(b3) : "l"(pp + 4));
                unsigned m = min(min(min(a0, a1), min(a2, a3)),
                                 min(min(b0, b1), min(b2, b3)));
                if (m >= tgt) break;
            }
            __threadfence();
        }
        __syncthreads();
    };

#pragma unroll 1
    for (int t = 0; t < Tn; t++) {
        const int p = t & 1;
        const __half* h2cur = g_h2h + p * BH;
        __half* h1nxt = g_h1h + (1 - p) * BH;
        __half* h2nxt = g_h2h + (1 - p) * BH;
        float* presc = prs + p * 2048;

        // ===== Phase A: layer-1 gates = hA @ W1^T (+ pre) =====
        // (no top sync: B-end sync of t-1 / init sync covers hA & G reuse)
        {
            float acc[2][4];
#pragma unroll
            for (int q = 0; q < 2; q++)
#pragma unroll
                for (int w = 0; w < 4; w++) acc[q][w] = 0.f;
            gemm_acc(ROF_HA, ROF_W1, acc);
            stage_G(acc);
        }
        CP_WAIT0();        // pre[t] landed (overlapped with the mma above)
        __syncthreads();   // G staged + pre visible
#pragma unroll
        for (int i = 0; i < 2; i++) {
            int b = bq + i;
            float iv = Gf[b * GS + u2]      + presc[b * 64 + u2];
            float fv = Gf[b * GS + 16 + u2] + presc[b * 64 + 16 + u2];
            float gv = Gf[b * GS + 32 + u2] + presc[b * 64 + 32 + u2];
            float ov = Gf[b * GS + 48 + u2] + presc[b * 64 + 48 + u2];
            int ci = b * 16 + u2;
            float cp = c1s[ci];
            float cn = sigf(fv) * cp + sigf(iv) * tanhfast(gv);
            c1s[ci] = cn;
            h1nxt[(bb * 32 + b) * Hn + ub * 16 + u2] = __float2half(sigf(ov) * tanhfast(cn));
        }
        group_barrier(sbase + (unsigned)t + 1u);

        // ===== Phase B: layer-2 gates = h1new @ Wi2^T + h2 @ Wh2^T + b2 =====
        {
#pragma unroll
            for (int i = 0; i < 2; i++) {
                int q = 2 * tid + i;
                int rr = q >> 4, ku = q & 15;
                uint32_t doff = (uint32_t)(rr * 256 + ((ku ^ (rr & 7)) << 4));
                CP16(sb + ROF_HA + doff, h1nxt + (bb * 32 + rr) * Hn + ku * 8);
                CP16(sb + ROF_HB + doff, h2cur + (bb * 32 + rr) * Hn + ku * 8);
            }
            CP_COMMIT();
        }
        if (t < Tn - 1) {   // prefetch pre[t+1], left in flight through phase B
#pragma unroll
            for (int i = 0; i < 2; i++) {
                int q = 2 * tid + i;
                int b = q >> 4, ch = q & 15;
                int gcol0 = ((ch >> 2) << 7) + (ub << 4) + (ch & 3) * 4;
                const float* src = pre + ((size_t)(t + 1) * Bn + bb * 32 + b) * G4 + gcol0;
                CP16(sb + ROF_PRE + (((t + 1) & 1) * 2048 + b * 64 + ch * 4) * 4, src);
            }
            CP_COMMIT();
            CP_WAIT1();
        } else {
            CP_WAIT0();
        }
        __syncthreads();
        {
            float acc[2][4];
#pragma unroll
            for (int q = 0; q < 2; q++)
#pragma unroll
                for (int w = 0; w < 4; w++) acc[q][w] = 0.f;
            gemm2_acc(ROF_HA, ROF_WI2, ROF_HB, ROF_WH2, acc);
            stage_G(acc);
        }
        __syncthreads();
#pragma unroll
        for (int i = 0; i < 2; i++) {
            int b = bq + i;
            float iv = Gf[b * GS + u2]      + b2s[u2];
            float fv = Gf[b * GS + 16 + u2] + b2s[16 + u2];
            float gv = Gf[b * GS + 32 + u2] + b2s[32 + u2];
            float ov = Gf[b * GS + 48 + u2] + b2s[48 + u2];
            int ci = b * 16 + u2;
            float cp = c2s[ci];
            float cn = sigf(fv) * cp + sigf(iv) * tanhfast(gv);
            c2s[ci] = cn;
            float hn = sigf(ov) * tanhfast(cn);
            h2nxt[(bb * 32 + b) * Hn + ub * 16 + u2] = __float2half(hn);
            if (t == Tn - 1)
                h2out[(bb * 32 + b) * Hn + ub * 16 + u2] = hn;
        }
        __syncthreads();   // B-end: protects G + hA reuse by phase A(t+1)
    }
}

// -------- launch --------
extern "C" void kernel_launch(void* const* d_in, const int* in_sizes, int n_in,
                              void* d_out, int out_size) {
    const float* feats = (const float*)d_in[0];
    const float* Wih1  = (const float*)d_in[1];
    const float* Whh1  = (const float*)d_in[2];
    const float* bih1  = (const float*)d_in[3];
    const float* bhh1  = (const float*)d_in[4];
    const float* Wih2  = (const float*)d_in[5];
    const float* Whh2  = (const float*)d_in[6];
    const float* bih2  = (const float*)d_in[7];
    const float* bhh2  = (const float*)d_in[8];

    float* pre;
    __half *Ah, *Wh;
    cudaGetSymbolAddress((void**)&pre, g_pre);
    cudaGetSymbolAddress((void**)&Ah,  g_Ah);
    cudaGetSymbolAddress((void**)&Wh,  g_Wh);

    static int attr_set = 0;
    if (!attr_set) {
        cudaFuncSetAttribute(lstm_persist,
                             cudaFuncAttributeMaxDynamicSharedMemorySize,
                             R_SMEM);
        attr_set = 1;
    }

    // fp32 -> fp16 staging
    cvt_fp16_kernel<<<4096, 256>>>(feats, Ah, (Bn * Tn * Dn) / 8);
    cvt_fp16_kernel<<<256, 256>>>(Wih1, Wh, (G4 * Dn) / 8);

    // pre = feats @ Wih1^T + bih1 + bhh1
    gemm_pre_mma<<<dim3(4, 512), 256>>>(Ah, Wh, bih1, bhh1, pre);

    lstm_persist<<<128, 256, R_SMEM>>>(
        pre, Whh1, Wih2, Whh2, bih2, bhh2, (float*)d_out);
}

// round 15
// speedup vs baseline: 1.0647x; 1.0647x over previous
#include <cuda_runtime.h>
#include <cuda_fp16.h>
#include <math.h>
#include <stdint.h>

// Problem dims
#define Tn 128
#define Bn 512
#define Dn 1024
#define Hn 128
#define G4 512   // 4*H
#define BH (Bn*Hn)

// -------- scratch (device globals: no allocations allowed) --------
__device__ float  g_pre[(size_t)Tn * Bn * G4];  // [t][b][4H]
__device__ __half g_Ah[(size_t)Bn * Tn * Dn];   // feats fp16
__device__ __half g_Wh[G4 * Dn];                // Wih1 fp16
__device__ __half g_h1h[2 * BH];                // fp16 h1 ping-pong
__device__ __half g_h2h[2 * BH];                // fp16 h2 ping-pong
__device__ __align__(32) unsigned g_stamp[16 * 8];  // per-group arrival stamps

// ============================================================================
// helpers
// ============================================================================
__device__ __forceinline__ uint32_t smem_u32(const void* p) {
    uint32_t a;
    asm("{ .reg .u64 t; cvta.to.shared.u64 t, %1; cvt.u32.u64 %0, t; }"
        : "=r"(a) : "l"(p));
    return a;
}

__device__ __forceinline__ void ldsm4(uint32_t* r, uint32_t addr) {
    asm volatile("ldmatrix.sync.aligned.m8n8.x4.shared.b16 {%0,%1,%2,%3}, [%4];"
                 : "=r"(r[0]), "=r"(r[1]), "=r"(r[2]), "=r"(r[3]) : "r"(addr));
}

__device__ __forceinline__ void mma16816h(float* d, const uint32_t* a, const uint32_t* b) {
    asm volatile(
        "mma.sync.aligned.m16n8k16.row.col.f32.f16.f16.f32 "
        "{%0,%1,%2,%3}, {%4,%5,%6,%7}, {%8,%9}, {%0,%1,%2,%3};"
        : "+f"(d[0]), "+f"(d[1]), "+f"(d[2]), "+f"(d[3])
        : "r"(a[0]), "r"(a[1]), "r"(a[2]), "r"(a[3]), "r"(b[0]), "r"(b[1]));
}

__device__ __forceinline__ uint4 pack8h(float4 v0, float4 v1) {
    __half2 h0 = __floats2half2_rn(v0.x, v0.y);
    __half2 h1 = __floats2half2_rn(v0.z, v0.w);
    __half2 h2 = __floats2half2_rn(v1.x, v1.y);
    __half2 h3 = __floats2half2_rn(v1.z, v1.w);
    return make_uint4(*(uint32_t*)&h0, *(uint32_t*)&h1,
                      *(uint32_t*)&h2, *(uint32_t*)&h3);
}

#define CP16(dst, src) \
    asm volatile("cp.async.cg.shared.global [%0], [%1], 16;" \
                 :: "r"(dst), "l"(src) : "memory")
#define CP_COMMIT() asm volatile("cp.async.commit_group;" ::: "memory")
#define CP_WAIT1()  asm volatile("cp.async.wait_group 1;" ::: "memory")
#define CP_WAIT0()  asm volatile("cp.async.wait_group 0;" ::: "memory")

// -------- fp32 -> fp16 bulk convert --------
__global__ void __launch_bounds__(256) cvt_fp16_kernel(
    const float* __restrict__ s, __half* __restrict__ d, int n8)
{
    int i = blockIdx.x * blockDim.x + threadIdx.x;
    int stride = gridDim.x * blockDim.x;
    for (; i < n8; i += stride) {
        const float4* sp = (const float4*)s + 2 * (size_t)i;
        *(uint4*)((char*)d + 16 * (size_t)i) = pack8h(sp[0], sp[1]);
    }
}

// ============================================================================
// pre-projection GEMM (unchanged, validated)
// ============================================================================
#define NSTG 3

__global__ void __launch_bounds__(256, 2) gemm_pre_mma(
    const __half* __restrict__ Ah,   // [65536][1024]
    const __half* __restrict__ Wh,   // [512][1024]
    const float* __restrict__ b1,    // [512]
    const float* __restrict__ b2,    // [512]
    float* __restrict__ out)         // [T][B][512]
{
    __shared__ __align__(128) char smbuf[NSTG * 16384];
    __shared__ float bias_s[128];

    const int tid  = threadIdx.x;
    const int lane = tid & 31;
    const int wid  = tid >> 5;
    const int n0 = blockIdx.x * 128;
    const int m0 = blockIdx.y * 128;
    const uint32_t sb = smem_u32(smbuf);

    if (tid < 128) bias_s[tid] = b1[n0 + tid] + b2[n0 + tid];

    const int r   = tid >> 1;
    const int u0  = (tid & 1) * 2;
    const int ssw = (r >> 1) & 3;
    const uint32_t so0 = r * 64 + (((u0)     ^ ssw) << 4);
    const uint32_t so1 = r * 64 + (((u0 + 1) ^ ssw) << 4);

    const __half* arow = Ah + (size_t)(m0 + r) * Dn;
    const __half* brow = Wh + (size_t)(n0 + r) * Dn;

    const int m0w = (wid >> 1) * 32;
    const int n0w = (wid & 1) * 64;

    const int rowA = m0w + (lane & 15);
    const int jA   = lane >> 4;
    const int swA  = (rowA >> 1) & 3;
    const uint32_t aA = sb + rowA * 64;
    const int rowB = n0w + (lane & 7) + ((lane >> 4) & 1) * 8;
    const int jB   = (lane >> 3) & 1;
    const int swB  = (rowB >> 1) & 3;
    const uint32_t aB = sb + 8192 + rowB * 64;

    float acc[2][8][4];
#pragma unroll
    for (int mi = 0; mi < 2; mi++)
#pragma unroll
        for (int ni = 0; ni < 8; ni++)
#pragma unroll
            for (int q = 0; q < 4; q++) acc[mi][ni][q] = 0.f;

    auto issue = [&](int kc, int stg) {
        const uint32_t d = sb + stg * 16384;
        const __half* as = arow + kc * 32 + u0 * 8;
        const __half* bs = brow + kc * 32 + u0 * 8;
        CP16(d + so0,        as);
        CP16(d + so1,        as + 8);
        CP16(d + 8192 + so0, bs);
        CP16(d + 8192 + so1, bs + 8);
        CP_COMMIT();
    };

    issue(0, 0);
    issue(1, 1);

#pragma unroll 1
    for (int kc = 0; kc < 32; kc++) {
        if (kc == 31) { CP_WAIT0(); } else { CP_WAIT1(); }
        __syncthreads();

        if (kc < 30) issue(kc + 2, (kc + 2) % NSTG);

        const uint32_t ba  = aA + (kc % NSTG) * 16384;
        const uint32_t bbb = aB + (kc % NSTG) * 16384;
#pragma unroll
        for (int kf = 0; kf < 2; kf++) {
            uint32_t Af[2][4], Bf[4][4];
            const int ja = (((2 * kf + jA) ^ swA) << 4);
            const int jb = (((2 * kf + jB) ^ swB) << 4);
            ldsm4(Af[0], ba + ja);
            ldsm4(Af[1], ba + 1024 + ja);
#pragma unroll
            for (int ng = 0; ng < 4; ng++)
                ldsm4(Bf[ng], bbb + ng * 1024 + jb);
#pragma unroll
            for (int mi = 0; mi < 2; mi++)
#pragma unroll
                for (int ni = 0; ni < 8; ni++)
                    mma16816h(acc[mi][ni], Af[mi], &Bf[ni >> 1][(ni & 1) * 2]);
        }
        __syncthreads();
    }

#pragma unroll
    for (int mi = 0; mi < 2; mi++) {
        int ma = m0 + m0w + mi * 16 + (lane >> 2);
        int mb = ma + 8;
        float* rowa = out + ((size_t)(ma & 127) * Bn + (ma >> 7)) * G4 + n0;
        float* rowb = out + ((size_t)(mb & 127) * Bn + (mb >> 7)) * G4 + n0;
#pragma unroll
        for (int ni = 0; ni < 8; ni++) {
            int nl = n0w + ni * 8 + (lane & 3) * 2;
            float bv0 = bias_s[nl], bv1 = bias_s[nl + 1];
            float2 v;
            v.x = acc[mi][ni][0] + bv0;
            v.y = acc[mi][ni][1] + bv1;
            *(float2*)(rowa + nl) = v;
            v.x = acc[mi][ni][2] + bv0;
            v.y = acc[mi][ni][3] + bv1;
            *(float2*)(rowb + nl) = v;
        }
    }
}

// ============================================================================
// persistent recurrence — r10 structure + stamp barrier + fused dual GEMM
// Grid: 128 CTAs = 16 batch-groups x 8 unit-CTAs (NO cluster launch).
// ============================================================================
__device__ __forceinline__ float sigf(float x) {
    return __fdividef(1.f, 1.f + __expf(-x));
}
__device__ __forceinline__ float tanhfast(float x) {
    return __fmaf_rn(2.f, __fdividef(1.f, 1.f + __expf(-2.f * x)), -1.f);
}

// SMEM byte offsets
#define ROF_W1   0          // Whh1 fp16 [64][128] swizzled, 16KB
#define ROF_WI2  16384
#define ROF_WH2  32768
#define ROF_HA   49152      // h1 tile [32][128] fp16 swizzled, 8KB
#define ROF_HB   57344      // h2 tile
#define ROF_G    65536      // gates fp32 [32][68]
#define ROF_PRE  74240      // pre fp32 [2][32][64]
#define ROF_C1   90624
#define ROF_C2   92672
#define ROF_B2   94720
#define R_SMEM   95040

#define GS 68   // G row stride (floats)

__global__ void __launch_bounds__(256, 1) lstm_persist(
    const float* __restrict__ pre,    // [T][B][512]
    const float* __restrict__ Whh1,   // [512][128]
    const float* __restrict__ Wih2,   // [512][128]
    const float* __restrict__ Whh2,   // [512][128]
    const float* __restrict__ bih2,   // [512]
    const float* __restrict__ bhh2,   // [512]
    float* __restrict__ h2out)        // [B][128] (d_out)
{
    extern __shared__ char sm[];
    const uint32_t sb = smem_u32(sm);
    const int tid  = threadIdx.x;
    const int lane = tid & 31;
    const int wid  = tid >> 5;
    const int bb   = blockIdx.x >> 3;   // 0..15 (barrier group)
    const int ub   = blockIdx.x & 7;    // 0..7

    float* Gf  = (float*)(sm + ROF_G);
    float* prs = (float*)(sm + ROF_PRE);
    float* c1s = (float*)(sm + ROF_C1);
    float* c2s = (float*)(sm + ROF_C2);
    float* b2s = (float*)(sm + ROF_B2);

    // stamp base: all 8 slots of the group are equal at launch boundaries
    const unsigned sbase = *(volatile unsigned*)&g_stamp[bb * 8 + ub];

    // ---- init: weights -> fp16 smem (swizzled), zero state ----
    for (int idx = tid; idx < 64 * 128; idx += 256) {
        int j = idx >> 7;
        int k = idx & 127;
        int gcol = ((j >> 4) << 7) + (ub << 4) + (j & 15);
        uint32_t ad = (uint32_t)(j * 256 + (((k >> 3) ^ (j & 7)) << 4) + (k & 7) * 2);
        *(__half*)(sm + ROF_W1  + ad) = __float2half(Whh1[(size_t)gcol * Hn + k]);
        *(__half*)(sm + ROF_WI2 + ad) = __float2half(Wih2[(size_t)gcol * Hn + k]);
        *(__half*)(sm + ROF_WH2 + ad) = __float2half(Whh2[(size_t)gcol * Hn + k]);
    }
    if (tid < 64) {
        int gcol = ((tid >> 4) << 7) + (ub << 4) + (tid & 15);
        b2s[tid] = bih2[gcol] + bhh2[gcol];
    }
    for (int i = tid; i < 512; i += 256) { c1s[i] = 0.f; c2s[i] = 0.f; }
    for (int i = tid; i < 2048; i += 256) ((uint32_t*)(sm + ROF_HA))[i] = 0;
    {
        int u = tid & 15;
        int bl = tid >> 4;
#pragma unroll
        for (int i = 0; i < 2; i++) {
            int row = bb * 32 + bl + i * 16;
            g_h1h[row * Hn + ub * 16 + u] = __float2half(0.f);
            g_h2h[row * Hn + ub * 16 + u] = __float2half(0.f);
        }
    }
    // prefetch pre[0] slice into pres buf 0
    {
#pragma unroll
        for (int i = 0; i < 2; i++) {
            int q = 2 * tid + i;
            int b = q >> 4, ch = q & 15;
            int gcol0 = ((ch >> 2) << 7) + (ub << 4) + (ch & 3) * 4;
            const float* src = pre + ((size_t)(bb * 32 + b)) * G4 + gcol0;
            CP16(sb + ROF_PRE + (b * 64 + ch * 4) * 4, src);
        }
        CP_COMMIT();
    }
    __syncthreads();   // init smem (weights, hA zeros) visible CTA-wide

    // ---- per-thread mma geometry (warp tile 16m x 16n; 2x4 warp grid) ----
    const int m_off = (wid >> 2) * 16;
    const int n_off = (wid & 3) * 16;
    const int rowA = m_off + (lane & 15);
    const uint32_t aoffA = rowA * 256;
    const int swA = rowA & 7;
    const int kuA0 = lane >> 4;
    const int rowB = n_off + (lane & 7) + ((lane >> 4) & 1) * 8;
    const uint32_t boffB = rowB * 256;
    const int swB = rowB & 7;
    const int kuB0 = (lane >> 3) & 1;

    const int u2 = tid & 15;
    const int bq = (tid >> 4) * 2;

    auto gemm_acc = [&](uint32_t hbase, uint32_t wbase, float acc[2][4]) {
#pragma unroll
        for (int ks = 0; ks < 8; ks++) {
            uint32_t Af[4], Bf[4];
            int kuA = 2 * ks + kuA0;
            int kuB = 2 * ks + kuB0;
            ldsm4(Af, sb + hbase + aoffA + (uint32_t)(((kuA ^ swA)) << 4));
            ldsm4(Bf, sb + wbase + boffB + (uint32_t)(((kuB ^ swB)) << 4));
            mma16816h(acc[0], Af, Bf);
            mma16816h(acc[1], Af, Bf + 2);
        }
    };
    // fused dual GEMM: acc += h1b@w1b^T + h2b@w2b^T  (4 ldsm + 4 mma per ks)
    auto gemm2_acc = [&](uint32_t h1b, uint32_t w1b, uint32_t h2b, uint32_t w2b,
                         float acc[2][4]) {
#pragma unroll
        for (int ks = 0; ks < 8; ks++) {
            uint32_t Af[4], Bf[4], Cf[4], Df[4];
            int kuA = 2 * ks + kuA0;
            int kuB = 2 * ks + kuB0;
            uint32_t oA = (uint32_t)(((kuA ^ swA)) << 4);
            uint32_t oB = (uint32_t)(((kuB ^ swB)) << 4);
            ldsm4(Af, sb + h1b + aoffA + oA);
            ldsm4(Bf, sb + w1b + boffB + oB);
            ldsm4(Cf, sb + h2b + aoffA + oA);
            ldsm4(Df, sb + w2b + boffB + oB);
            mma16816h(acc[0], Af, Bf);
            mma16816h(acc[1], Af, Bf + 2);
            mma16816h(acc[0], Cf, Df);
            mma16816h(acc[1], Cf, Df + 2);
        }
    };
    auto stage_G = [&](float acc[2][4]) {
        int r0 = m_off + (lane >> 2);
        int c0 = n_off + 2 * (lane & 3);
#pragma unroll
        for (int h = 0; h < 2; h++) {
            Gf[r0 * GS + c0 + 8 * h]           = acc[h][0];
            Gf[r0 * GS + c0 + 8 * h + 1]       = acc[h][1];
            Gf[(r0 + 8) * GS + c0 + 8 * h]     = acc[h][2];
            Gf[(r0 + 8) * GS + c0 + 8 * h + 1] = acc[h][3];
        }
    };

    // stamp barrier: release own slot, poll all 8, acquire
    auto group_barrier = [&](unsigned tgt) {
        __syncthreads();
        if (tid == 0) {
            __threadfence();
            asm volatile("st.release.gpu.global.u32 [%0], %1;"
                         :: "l"(&g_stamp[bb * 8 + ub]), "r"(tgt) : "memory");
            const unsigned* pp = &g_stamp[bb * 8];
            while (true) {
                unsigned a0, a1, a2, a3, b0, b1, b2, b3;
                asm volatile("ld.volatile.global.v4.u32 {%0,%1,%2,%3}, [%4];"
                             : "=r"(a0), "=r"(a1), "=r"(a2), "=r"(a3) : "l"(pp));
                asm volatile("ld.volatile.global.v4.u32 {%0,%1,%2,%3}, [%4];"
                             : "=r"(b0), "=r"(b1), "=r"(b2), "=r"(b3) : "l"(pp + 4));
                unsigned m = min(min(min(a0, a1), min(a2, a3)),
                                 min(min(b0, b1), min(b2, b3)));
                if (m >= tgt) break;
            }
            __threadfence();
        }
        __syncthreads();
    };

#pragma unroll 1
    for (int t = 0; t < Tn; t++) {
        const int p = t & 1;
        const __half* h2cur = g_h2h + p * BH;
        __half* h1nxt = g_h1h + (1 - p) * BH;
        __half* h2nxt = g_h2h + (1 - p) * BH;
        float* presc = prs + p * 2048;

        // ===== Phase A: layer-1 gates = hA @ W1^T (+ pre) =====
        // (no top sync: B-end sync of t-1 / init sync covers hA & G reuse)
        {
            float acc[2][4];
#pragma unroll
            for (int q = 0; q < 2; q++)
#pragma unroll
                for (int w = 0; w < 4; w++) acc[q][w] = 0.f;
            gemm_acc(ROF_HA, ROF_W1, acc);
            stage_G(acc);
        }
        CP_WAIT0();        // pre[t] landed (overlapped with the mma above)
        __syncthreads();   // G staged + pre visible
#pragma unroll
        for (int i = 0; i < 2; i++) {
            int b = bq + i;
            float iv = Gf[b * GS + u2]      + presc[b * 64 + u2];
            float fv = Gf[b * GS + 16 + u2] + presc[b * 64 + 16 + u2];
            float gv = Gf[b * GS + 32 + u2] + presc[b * 64 + 32 + u2];
            float ov = Gf[b * GS + 48 + u2] + presc[b * 64 + 48 + u2];
            int ci = b * 16 + u2;
            float cp = c1s[ci];
            float cn = sigf(fv) * cp + sigf(iv) * tanhfast(gv);
            c1s[ci] = cn;
            h1nxt[(bb * 32 + b) * Hn + ub * 16 + u2] = __float2half(sigf(ov) * tanhfast(cn));
        }
        group_barrier(sbase + (unsigned)t + 1u);

        // ===== Phase B: layer-2 gates = h1new @ Wi2^T + h2 @ Wh2^T + b2 =====
        {
#pragma unroll
            for (int i = 0; i < 2; i++) {
                int q = 2 * tid + i;
                int rr = q >> 4, ku = q & 15;
                uint32_t doff = (uint32_t)(rr * 256 + ((ku ^ (rr & 7)) << 4));
                CP16(sb + ROF_HA + doff, h1nxt + (bb * 32 + rr) * Hn + ku * 8);
                CP16(sb + ROF_HB + doff, h2cur + (bb * 32 + rr) * Hn + ku * 8);
            }
            CP_COMMIT();
        }
        if (t < Tn - 1) {   // prefetch pre[t+1], left in flight through phase B
#pragma unroll
            for (int i = 0; i < 2; i++) {
                int q = 2 * tid + i;
                int b = q >> 4, ch = q & 15;
                int gcol0 = ((ch >> 2) << 7) + (ub << 4) + (ch & 3) * 4;
                const float* src = pre + ((size_t)(t + 1) * Bn + bb * 32 + b) * G4 + gcol0;
                CP16(sb + ROF_PRE + (((t + 1) & 1) * 2048 + b * 64 + ch * 4) * 4, src);
            }
            CP_COMMIT();
            CP_WAIT1();
        } else {
            CP_WAIT0();
        }
        __syncthreads();
        {
            float acc[2][4];
#pragma unroll
            for (int q = 0; q < 2; q++)
#pragma unroll
                for (int w = 0; w < 4; w++) acc[q][w] = 0.f;
            gemm2_acc(ROF_HA, ROF_WI2, ROF_HB, ROF_WH2, acc);
            stage_G(acc);
        }
        __syncthreads();
#pragma unroll
        for (int i = 0; i < 2; i++) {
            int b = bq + i;
            float iv = Gf[b * GS + u2]      + b2s[u2];
            float fv = Gf[b * GS + 16 + u2] + b2s[16 + u2];
            float gv = Gf[b * GS + 32 + u2] + b2s[32 + u2];
            float ov = Gf[b * GS + 48 + u2] + b2s[48 + u2];
            int ci = b * 16 + u2;
            float cp = c2s[ci];
            float cn = sigf(fv) * cp + sigf(iv) * tanhfast(gv);
            c2s[ci] = cn;
            float hn = sigf(ov) * tanhfast(cn);
            h2nxt[(bb * 32 + b) * Hn + ub * 16 + u2] = __float2half(hn);
            if (t == Tn - 1)
                h2out[(bb * 32 + b) * Hn + ub * 16 + u2] = hn;
        }
        __syncthreads();   // B-end: protects G + hA reuse by phase A(t+1)
    }
}

// -------- launch --------
extern "C" void kernel_launch(void* const* d_in, const int* in_sizes, int n_in,
                              void* d_out, int out_size) {
    const float* feats = (const float*)d_in[0];
    const float* Wih1  = (const float*)d_in[1];
    const float* Whh1  = (const float*)d_in[2];
    const float* bih1  = (const float*)d_in[3];
    const float* bhh1  = (const float*)d_in[4];
    const float* Wih2  = (const float*)d_in[5];
    const float* Whh2  = (const float*)d_in[6];
    const float* bih2  = (const float*)d_in[7];
    const float* bhh2  = (const float*)d_in[8];

    float* pre;
    __half *Ah, *Wh;
    cudaGetSymbolAddress((void**)&pre, g_pre);
    cudaGetSymbolAddress((void**)&Ah,  g_Ah);
    cudaGetSymbolAddress((void**)&Wh,  g_Wh);

    static int attr_set = 0;
    if (!attr_set) {
        cudaFuncSetAttribute(lstm_persist,
                             cudaFuncAttributeMaxDynamicSharedMemorySize,
                             R_SMEM);
        attr_set = 1;
    }

    // fp32 -> fp16 staging
    cvt_fp16_kernel<<<4096, 256>>>(feats, Ah, (Bn * Tn * Dn) / 8);
    cvt_fp16_kernel<<<256, 256>>>(Wih1, Wh, (G4 * Dn) / 8);

    // pre = feats @ Wih1^T + bih1 + bhh1
    gemm_pre_mma<<<dim3(4, 512), 256>>>(Ah, Wh, bih1, bhh1, pre);

    lstm_persist<<<128, 256, R_SMEM>>>(
        pre, Whh1, Wih2, Whh2, bih2, bhh2, (float*)d_out);
}

// round 16
// speedup vs baseline: 1.9665x; 1.8470x over previous
#include <cuda_runtime.h>
#include <cuda_fp16.h>
#include <math.h>
#include <stdint.h>

// Problem dims
#define Tn 128
#define Bn 512
#define Dn 1024
#define Hn 128
#define G4 512   // 4*H
#define BH (Bn*Hn)

// -------- scratch (device globals: no allocations allowed) --------
__device__ float  g_pre[(size_t)Tn * Bn * G4];  // [t][b][4H]
__device__ __half g_Ah[(size_t)Bn * Tn * Dn];   // feats fp16
__device__ __half g_Wh[G4 * Dn];                // Wih1 fp16
__device__ __half g_h1h[2 * BH];                // fp16 h1 ping-pong
__device__ __half g_h2h[2 * BH];                // fp16 h2 ping-pong
__device__ unsigned g_gcnt[16 * 32];            // per-group barrier counters (128B apart)
__device__ unsigned g_ggen[16 * 32];            // per-group generations

// ============================================================================
// helpers
// ============================================================================
__device__ __forceinline__ uint32_t smem_u32(const void* p) {
    uint32_t a;
    asm("{ .reg .u64 t; cvta.to.shared.u64 t, %1; cvt.u32.u64 %0, t; }"
        : "=r"(a) : "l"(p));
    return a;
}

__device__ __forceinline__ void ldsm4(uint32_t* r, uint32_t addr) {
    asm volatile("ldmatrix.sync.aligned.m8n8.x4.shared.b16 {%0,%1,%2,%3}, [%4];"
                 : "=r"(r[0]), "=r"(r[1]), "=r"(r[2]), "=r"(r[3]) : "r"(addr));
}

__device__ __forceinline__ void mma16816h(float* d, const uint32_t* a, const uint32_t* b) {
    asm volatile(
        "mma.sync.aligned.m16n8k16.row.col.f32.f16.f16.f32 "
        "{%0,%1,%2,%3}, {%4,%5,%6,%7}, {%8,%9}, {%0,%1,%2,%3};"
        : "+f"(d[0]), "+f"(d[1]), "+f"(d[2]), "+f"(d[3])
        : "r"(a[0]), "r"(a[1]), "r"(a[2]), "r"(a[3]), "r"(b[0]), "r"(b[1]));
}

__device__ __forceinline__ uint4 pack8h(float4 v0, float4 v1) {
    __half2 h0 = __floats2half2_rn(v0.x, v0.y);
    __half2 h1 = __floats2half2_rn(v0.z, v0.w);
    __half2 h2 = __floats2half2_rn(v1.x, v1.y);
    __half2 h3 = __floats2half2_rn(v1.z, v1.w);
    return make_uint4(*(uint32_t*)&h0, *(uint32_t*)&h1,
                      *(uint32_t*)&h2, *(uint32_t*)&h3);
}

#define CP16(dst, src) \
    asm volatile("cp.async.cg.shared.global [%0], [%1], 16;" \
                 :: "r"(dst), "l"(src) : "memory")
#define CP_COMMIT() asm volatile("cp.async.commit_group;" ::: "memory")
#define CP_WAIT1()  asm volatile("cp.async.wait_group 1;" ::: "memory")
#define CP_WAIT0()  asm volatile("cp.async.wait_group 0;" ::: "memory")

// -------- fp32 -> fp16 bulk convert --------
__global__ void __launch_bounds__(256) cvt_fp16_kernel(
    const float* __restrict__ s, __half* __restrict__ d, int n8)
{
    int i = blockIdx.x * blockDim.x + threadIdx.x;
    int stride = gridDim.x * blockDim.x;
    for (; i < n8; i += stride) {
        const float4* sp = (const float4*)s + 2 * (size_t)i;
        *(uint4*)((char*)d + 16 * (size_t)i) = pack8h(sp[0], sp[1]);
    }
}

// ============================================================================
// pre-projection GEMM (unchanged, validated)
// ============================================================================
#define NSTG 3

__global__ void __launch_bounds__(256, 2) gemm_pre_mma(
    const __half* __restrict__ Ah,   // [65536][1024]
    const __half* __restrict__ Wh,   // [512][1024]
    const float* __restrict__ b1,    // [512]
    const float* __restrict__ b2,    // [512]
    float* __restrict__ out)         // [T][B][512]
{
    __shared__ __align__(128) char smbuf[NSTG * 16384];
    __shared__ float bias_s[128];

    const int tid  = threadIdx.x;
    const int lane = tid & 31;
    const int wid  = tid >> 5;
    const int n0 = blockIdx.x * 128;
    const int m0 = blockIdx.y * 128;
    const uint32_t sb = smem_u32(smbuf);

    if (tid < 128) bias_s[tid] = b1[n0 + tid] + b2[n0 + tid];

    const int r   = tid >> 1;
    const int u0  = (tid & 1) * 2;
    const int ssw = (r >> 1) & 3;
    const uint32_t so0 = r * 64 + (((u0)     ^ ssw) << 4);
    const uint32_t so1 = r * 64 + (((u0 + 1) ^ ssw) << 4);

    const __half* arow = Ah + (size_t)(m0 + r) * Dn;
    const __half* brow = Wh + (size_t)(n0 + r) * Dn;

    const int m0w = (wid >> 1) * 32;
    const int n0w = (wid & 1) * 64;

    const int rowA = m0w + (lane & 15);
    const int jA   = lane >> 4;
    const int swA  = (rowA >> 1) & 3;
    const uint32_t aA = sb + rowA * 64;
    const int rowB = n0w + (lane & 7) + ((lane >> 4) & 1) * 8;
    const int jB   = (lane >> 3) & 1;
    const int swB  = (rowB >> 1) & 3;
    const uint32_t aB = sb + 8192 + rowB * 64;

    float acc[2][8][4];
#pragma unroll
    for (int mi = 0; mi < 2; mi++)
#pragma unroll
        for (int ni = 0; ni < 8; ni++)
#pragma unroll
            for (int q = 0; q < 4; q++) acc[mi][ni][q] = 0.f;

    auto issue = [&](int kc, int stg) {
        const uint32_t d = sb + stg * 16384;
        const __half* as = arow + kc * 32 + u0 * 8;
        const __half* bs = brow + kc * 32 + u0 * 8;
        CP16(d + so0,        as);
        CP16(d + so1,        as + 8);
        CP16(d + 8192 + so0, bs);
        CP16(d + 8192 + so1, bs + 8);
        CP_COMMIT();
    };

    issue(0, 0);
    issue(1, 1);

#pragma unroll 1
    for (int kc = 0; kc < 32; kc++) {
        if (kc == 31) { CP_WAIT0(); } else { CP_WAIT1(); }
        __syncthreads();

        if (kc < 30) issue(kc + 2, (kc + 2) % NSTG);

        const uint32_t ba  = aA + (kc % NSTG) * 16384;
        const uint32_t bbb = aB + (kc % NSTG) * 16384;
#pragma unroll
        for (int kf = 0; kf < 2; kf++) {
            uint32_t Af[2][4], Bf[4][4];
            const int ja = (((2 * kf + jA) ^ swA) << 4);
            const int jb = (((2 * kf + jB) ^ swB) << 4);
            ldsm4(Af[0], ba + ja);
            ldsm4(Af[1], ba + 1024 + ja);
#pragma unroll
            for (int ng = 0; ng < 4; ng++)
                ldsm4(Bf[ng], bbb + ng * 1024 + jb);
#pragma unroll
            for (int mi = 0; mi < 2; mi++)
#pragma unroll
                for (int ni = 0; ni < 8; ni++)
                    mma16816h(acc[mi][ni], Af[mi], &Bf[ni >> 1][(ni & 1) * 2]);
        }
        __syncthreads();
    }

#pragma unroll
    for (int mi = 0; mi < 2; mi++) {
        int ma = m0 + m0w + mi * 16 + (lane >> 2);
        int mb = ma + 8;
        float* rowa = out + ((size_t)(ma & 127) * Bn + (ma >> 7)) * G4 + n0;
        float* rowb = out + ((size_t)(mb & 127) * Bn + (mb >> 7)) * G4 + n0;
#pragma unroll
        for (int ni = 0; ni < 8; ni++) {
            int nl = n0w + ni * 8 + (lane & 3) * 2;
            float bv0 = bias_s[nl], bv1 = bias_s[nl + 1];
            float2 v;
            v.x = acc[mi][ni][0] + bv0;
            v.y = acc[mi][ni][1] + bv1;
            *(float2*)(rowa + nl) = v;
            v.x = acc[mi][ni][2] + bv0;
            v.y = acc[mi][ni][3] + bv1;
            *(float2*)(rowb + nl) = v;
        }
    }
}

// ============================================================================
// persistent recurrence — r10 structure (ticket barrier) + intra-CTA tweaks:
//   (1) phase-A: no top sync; CP_WAIT0 for pre[t] moved after the mma
//   (2) phase-B: fused dual GEMM (Wi2@h1 interleaved with Wh2@h2)
// Grid: 128 CTAs = 16 batch-groups x 8 unit-CTAs.
// ============================================================================
__device__ __forceinline__ float sigf(float x) {
    return __fdividef(1.f, 1.f + __expf(-x));
}
__device__ __forceinline__ float tanhfast(float x) {
    return __fmaf_rn(2.f, __fdividef(1.f, 1.f + __expf(-2.f * x)), -1.f);
}

// r10-measured ticket barrier (8 CTAs per group)
__device__ __forceinline__ void group_barrier(int grp) {
    __syncthreads();
    if (threadIdx.x == 0) {
        const int s = grp * 32;
        __threadfence();
        unsigned gen = *(volatile unsigned*)&g_ggen[s];
        unsigned ticket = atomicAdd(&g_gcnt[s], 1);
        if (ticket == 7) {
            *(volatile unsigned*)&g_gcnt[s] = 0;
            __threadfence();
            atomicAdd(&g_ggen[s], 1);
        } else {
            while (*(volatile unsigned*)&g_ggen[s] == gen) { __nanosleep(20); }
            __threadfence();
        }
    }
    __syncthreads();
}

// SMEM byte offsets
#define ROF_W1   0          // Whh1 fp16 [64][128] swizzled, 16KB
#define ROF_WI2  16384
#define ROF_WH2  32768
#define ROF_HA   49152      // h1 tile [32][128] fp16 swizzled, 8KB
#define ROF_HB   57344      // h2 tile
#define ROF_G    65536      // gates fp32 [32][68]
#define ROF_PRE  74240      // pre fp32 [2][32][64]
#define ROF_C1   90624
#define ROF_C2   92672
#define ROF_B2   94720
#define R_SMEM   95040

#define GS 68   // G row stride (floats)

__global__ void __launch_bounds__(256, 1) lstm_persist(
    const float* __restrict__ pre,    // [T][B][512]
    const float* __restrict__ Whh1,   // [512][128]
    const float* __restrict__ Wih2,   // [512][128]
    const float* __restrict__ Whh2,   // [512][128]
    const float* __restrict__ bih2,   // [512]
    const float* __restrict__ bhh2,   // [512]
    float* __restrict__ h2out)        // [B][128] (d_out)
{
    extern __shared__ char sm[];
    const uint32_t sb = smem_u32(sm);
    const int tid  = threadIdx.x;
    const int lane = tid & 31;
    const int wid  = tid >> 5;
    const int bb   = blockIdx.x >> 3;   // 0..15 (barrier group)
    const int ub   = blockIdx.x & 7;    // 0..7

    float* Gf  = (float*)(sm + ROF_G);
    float* prs = (float*)(sm + ROF_PRE);
    float* c1s = (float*)(sm + ROF_C1);
    float* c2s = (float*)(sm + ROF_C2);
    float* b2s = (float*)(sm + ROF_B2);

    // ---- init: weights -> fp16 smem (swizzled), zero state ----
    for (int idx = tid; idx < 64 * 128; idx += 256) {
        int j = idx >> 7;
        int k = idx & 127;
        int gcol = ((j >> 4) << 7) + (ub << 4) + (j & 15);
        uint32_t ad = (uint32_t)(j * 256 + (((k >> 3) ^ (j & 7)) << 4) + (k & 7) * 2);
        *(__half*)(sm + ROF_W1  + ad) = __float2half(Whh1[(size_t)gcol * Hn + k]);
        *(__half*)(sm + ROF_WI2 + ad) = __float2half(Wih2[(size_t)gcol * Hn + k]);
        *(__half*)(sm + ROF_WH2 + ad) = __float2half(Whh2[(size_t)gcol * Hn + k]);
    }
    if (tid < 64) {
        int gcol = ((tid >> 4) << 7) + (ub << 4) + (tid & 15);
        b2s[tid] = bih2[gcol] + bhh2[gcol];
    }
    for (int i = tid; i < 512; i += 256) { c1s[i] = 0.f; c2s[i] = 0.f; }
    for (int i = tid; i < 2048; i += 256) ((uint32_t*)(sm + ROF_HA))[i] = 0;
    {
        int u = tid & 15;
        int bl = tid >> 4;
#pragma unroll
        for (int i = 0; i < 2; i++) {
            int row = bb * 32 + bl + i * 16;
            g_h1h[row * Hn + ub * 16 + u] = __float2half(0.f);
            g_h2h[row * Hn + ub * 16 + u] = __float2half(0.f);
        }
    }
    // prefetch pre[0] slice into pres buf 0
    {
#pragma unroll
        for (int i = 0; i < 2; i++) {
            int q = 2 * tid + i;
            int b = q >> 4, ch = q & 15;
            int gcol0 = ((ch >> 2) << 7) + (ub << 4) + (ch & 3) * 4;
            const float* src = pre + ((size_t)(bb * 32 + b)) * G4 + gcol0;
            CP16(sb + ROF_PRE + (b * 64 + ch * 4) * 4, src);
        }
        CP_COMMIT();
    }
    group_barrier(bb);

    // ---- per-thread mma geometry (warp tile 16m x 16n; 2x4 warp grid) ----
    const int m_off = (wid >> 2) * 16;
    const int n_off = (wid & 3) * 16;
    const int rowA = m_off + (lane & 15);
    const uint32_t aoffA = rowA * 256;
    const int swA = rowA & 7;
    const int kuA0 = lane >> 4;
    const int rowB = n_off + (lane & 7) + ((lane >> 4) & 1) * 8;
    const uint32_t boffB = rowB * 256;
    const int swB = rowB & 7;
    const int kuB0 = (lane >> 3) & 1;

    const int u2 = tid & 15;
    const int bq = (tid >> 4) * 2;

    auto gemm_acc = [&](uint32_t hbase, uint32_t wbase, float acc[2][4]) {
#pragma unroll
        for (int ks = 0; ks < 8; ks++) {
            uint32_t Af[4], Bf[4];
            int kuA = 2 * ks + kuA0;
            int kuB = 2 * ks + kuB0;
            ldsm4(Af, sb + hbase + aoffA + (uint32_t)(((kuA ^ swA)) << 4));
            ldsm4(Bf, sb + wbase + boffB + (uint32_t)(((kuB ^ swB)) << 4));
            mma16816h(acc[0], Af, Bf);
            mma16816h(acc[1], Af, Bf + 2);
        }
    };
    // fused dual GEMM: acc += h1b@w1b^T + h2b@w2b^T (4 ldsm + 4 mma per ks)
    auto gemm2_acc = [&](uint32_t h1b, uint32_t w1b, uint32_t h2b, uint32_t w2b,
                         float acc[2][4]) {
#pragma unroll
        for (int ks = 0; ks < 8; ks++) {
            uint32_t Af[4], Bf[4], Cf[4], Df[4];
            int kuA = 2 * ks + kuA0;
            int kuB = 2 * ks + kuB0;
            uint32_t oA = (uint32_t)(((kuA ^ swA)) << 4);
            uint32_t oB = (uint32_t)(((kuB ^ swB)) << 4);
            ldsm4(Af, sb + h1b + aoffA + oA);
            ldsm4(Bf, sb + w1b + boffB + oB);
            ldsm4(Cf, sb + h2b + aoffA + oA);
            ldsm4(Df, sb + w2b + boffB + oB);
            mma16816h(acc[0], Af, Bf);
            mma16816h(acc[1], Af, Bf + 2);
            mma16816h(acc[0], Cf, Df);
            mma16816h(acc[1], Cf, Df + 2);
        }
    };
    auto stage_G = [&](float acc[2][4]) {
        int r0 = m_off + (lane >> 2);
        int c0 = n_off + 2 * (lane & 3);
#pragma unroll
        for (int h = 0; h < 2; h++) {
            Gf[r0 * GS + c0 + 8 * h]           = acc[h][0];
            Gf[r0 * GS + c0 + 8 * h + 1]       = acc[h][1];
            Gf[(r0 + 8) * GS + c0 + 8 * h]     = acc[h][2];
            Gf[(r0 + 8) * GS + c0 + 8 * h + 1] = acc[h][3];
        }
    };

#pragma unroll 1
    for (int t = 0; t < Tn; t++) {
        const int p = t & 1;
        const __half* h2cur = g_h2h + p * BH;
        __half* h1nxt = g_h1h + (1 - p) * BH;
        __half* h2nxt = g_h2h + (1 - p) * BH;
        float* presc = prs + p * 2048;

        // ===== Phase A: layer-1 gates = hA @ W1^T (+ pre) =====
        // hA holds h1(t) tile (cp.async-waited in phase B of t-1; zeros at t=0).
        // No top sync: B-end sync of t-1 (or init barrier) orders hA/G reuse.
        {
            float acc[2][4];
#pragma unroll
            for (int q = 0; q < 2; q++)
#pragma unroll
                for (int w = 0; w < 4; w++) acc[q][w] = 0.f;
            gemm_acc(ROF_HA, ROF_W1, acc);
            stage_G(acc);
        }
        CP_WAIT0();        // pre[t] landed (load overlapped the mma above)
        __syncthreads();   // G staged + pre visible
#pragma unroll
        for (int i = 0; i < 2; i++) {
            int b = bq + i;
            float iv = Gf[b * GS + u2]      + presc[b * 64 + u2];
            float fv = Gf[b * GS + 16 + u2] + presc[b * 64 + 16 + u2];
            float gv = Gf[b * GS + 32 + u2] + presc[b * 64 + 32 + u2];
            float ov = Gf[b * GS + 48 + u2] + presc[b * 64 + 48 + u2];
            int ci = b * 16 + u2;
            float cp = c1s[ci];
            float cn = sigf(fv) * cp + sigf(iv) * tanhfast(gv);
            c1s[ci] = cn;
            h1nxt[(bb * 32 + b) * Hn + ub * 16 + u2] = __float2half(sigf(ov) * tanhfast(cn));
        }
        group_barrier(bb);

        // ===== Phase B: layer-2 gates = h1new @ Wi2^T + h2 @ Wh2^T + b2 =====
        {
#pragma unroll
            for (int i = 0; i < 2; i++) {
                int q = 2 * tid + i;
                int rr = q >> 4, ku = q & 15;
                uint32_t doff = (uint32_t)(rr * 256 + ((ku ^ (rr & 7)) << 4));
                CP16(sb + ROF_HA + doff, h1nxt + (bb * 32 + rr) * Hn + ku * 8);
                CP16(sb + ROF_HB + doff, h2cur + (bb * 32 + rr) * Hn + ku * 8);
            }
            CP_COMMIT();
        }
        if (t < Tn - 1) {   // prefetch pre[t+1], left in flight through phase B
#pragma unroll
            for (int i = 0; i < 2; i++) {
                int q = 2 * tid + i;
                int b = q >> 4, ch = q & 15;
                int gcol0 = ((ch >> 2) << 7) + (ub << 4) + (ch & 3) * 4;
                const float* src = pre + ((size_t)(t + 1) * Bn + bb * 32 + b) * G4 + gcol0;
                CP16(sb + ROF_PRE + (((t + 1) & 1) * 2048 + b * 64 + ch * 4) * 4, src);
            }
            CP_COMMIT();
            CP_WAIT1();
        } else {
            CP_WAIT0();
        }
        __syncthreads();
        {
            float acc[2][4];
#pragma unroll
            for (int q = 0; q < 2; q++)
#pragma unroll
                for (int w = 0; w < 4; w++) acc[q][w] = 0.f;
            gemm2_acc(ROF_HA, ROF_WI2, ROF_HB, ROF_WH2, acc);
            stage_G(acc);
        }
        __syncthreads();
#pragma unroll
        for (int i = 0; i < 2; i++) {
            int b = bq + i;
            float iv = Gf[b * GS + u2]      + b2s[u2];
            float fv = Gf[b * GS + 16 + u2] + b2s[16 + u2];
            float gv = Gf[b * GS + 32 + u2] + b2s[32 + u2];
            float ov = Gf[b * GS + 48 + u2] + b2s[48 + u2];
            int ci = b * 16 + u2;
            float cp = c2s[ci];
            float cn = sigf(fv) * cp + sigf(iv) * tanhfast(gv);
            c2s[ci] = cn;
            float hn = sigf(ov) * tanhfast(cn);
            h2nxt[(bb * 32 + b) * Hn + ub * 16 + u2] = __float2half(hn);
            if (t == Tn - 1)
                h2out[(bb * 32 + b) * Hn + ub * 16 + u2] = hn;
        }
        __syncthreads();   // B-end: protects G + hA reuse by phase A(t+1)
    }
}

// -------- launch --------
extern "C" void kernel_launch(void* const* d_in, const int* in_sizes, int n_in,
                              void* d_out, int out_size) {
    const float* feats = (const float*)d_in[0];
    const float* Wih1  = (const float*)d_in[1];
    const float* Whh1  = (const float*)d_in[2];
    const float* bih1  = (const float*)d_in[3];
    const float* bhh1  = (const float*)d_in[4];
    const float* Wih2  = (const float*)d_in[5];
    const float* Whh2  = (const float*)d_in[6];
    const float* bih2  = (const float*)d_in[7];
    const float* bhh2  = (const float*)d_in[8];

    float* pre;
    __half *Ah, *Wh;
    cudaGetSymbolAddress((void**)&pre, g_pre);
    cudaGetSymbolAddress((void**)&Ah,  g_Ah);
    cudaGetSymbolAddress((void**)&Wh,  g_Wh);

    static int attr_set = 0;
    if (!attr_set) {
        cudaFuncSetAttribute(lstm_persist,
                             cudaFuncAttributeMaxDynamicSharedMemorySize,
                             R_SMEM);
        attr_set = 1;
    }

    // fp32 -> fp16 staging
    cvt_fp16_kernel<<<4096, 256>>>(feats, Ah, (Bn * Tn * Dn) / 8);
    cvt_fp16_kernel<<<256, 256>>>(Wih1, Wh, (G4 * Dn) / 8);

    // pre = feats @ Wih1^T + bih1 + bhh1
    gemm_pre_mma<<<dim3(4, 512), 256>>>(Ah, Wh, bih1, bhh1, pre);

    lstm_persist<<<128, 256, R_SMEM>>>(
        pre, Whh1, Wih2, Whh2, bih2, bhh2, (float*)d_out);
}

// round 17
// speedup vs baseline: 2.1880x; 1.1126x over previous
#include <cuda_runtime.h>
#include <cuda_fp16.h>
#include <math.h>
#include <stdint.h>

// Problem dims
#define Tn 128
#define Bn 512
#define Dn 1024
#define Hn 128
#define G4 512   // 4*H
#define BH (Bn*Hn)

#define NRCTA 128   // recurrence CTAs
#define NWORK 148   // pre-GEMM worker CTAs
#define NTILE 2048  // 128 t x 4 bblk x 4 ntile

// -------- scratch (device globals: no allocations allowed) --------
__device__ float  g_pre[(size_t)Tn * Bn * G4];  // [t][b][4H]
__device__ __half g_Ah[(size_t)Bn * Tn * Dn];   // feats fp16
__device__ __half g_Wh[G4 * Dn];                // Wih1 fp16
__device__ __half g_h1h[2 * BH];                // fp16 h1 ping-pong
__device__ __half g_h2h[2 * BH];                // fp16 h2 ping-pong
__device__ unsigned g_gcnt[16 * 32];            // per-group barrier counters
__device__ unsigned g_ggen[16 * 32];            // per-group generations
__device__ unsigned g_prog[Tn];                 // tiles finished per timestep (target 16)

// ============================================================================
// helpers
// ============================================================================
__device__ __forceinline__ uint32_t smem_u32(const void* p) {
    uint32_t a;
    asm("{ .reg .u64 t; cvta.to.shared.u64 t, %1; cvt.u32.u64 %0, t; }"
        : "=r"(a) : "l"(p));
    return a;
}

__device__ __forceinline__ void ldsm4(uint32_t* r, uint32_t addr) {
    asm volatile("ldmatrix.sync.aligned.m8n8.x4.shared.b16 {%0,%1,%2,%3}, [%4];"
                 : "=r"(r[0]), "=r"(r[1]), "=r"(r[2]), "=r"(r[3]) : "r"(addr));
}

__device__ __forceinline__ void mma16816h(float* d, const uint32_t* a, const uint32_t* b) {
    asm volatile(
        "mma.sync.aligned.m16n8k16.row.col.f32.f16.f16.f32 "
        "{%0,%1,%2,%3}, {%4,%5,%6,%7}, {%8,%9}, {%0,%1,%2,%3};"
        : "+f"(d[0]), "+f"(d[1]), "+f"(d[2]), "+f"(d[3])
        : "r"(a[0]), "r"(a[1]), "r"(a[2]), "r"(a[3]), "r"(b[0]), "r"(b[1]));
}

__device__ __forceinline__ uint4 pack8h(float4 v0, float4 v1) {
    __half2 h0 = __floats2half2_rn(v0.x, v0.y);
    __half2 h1 = __floats2half2_rn(v0.z, v0.w);
    __half2 h2 = __floats2half2_rn(v1.x, v1.y);
    __half2 h3 = __floats2half2_rn(v1.z, v1.w);
    return make_uint4(*(uint32_t*)&h0, *(uint32_t*)&h1,
                      *(uint32_t*)&h2, *(uint32_t*)&h3);
}

__device__ __forceinline__ unsigned ld_acq(const unsigned* p) {
    unsigned v;
    asm volatile("ld.acquire.gpu.global.u32 %0, [%1];" : "=r"(v) : "l"(p));
    return v;
}

#define CP16(dst, src) \
    asm volatile("cp.async.cg.shared.global [%0], [%1], 16;" \
                 :: "r"(dst), "l"(src) : "memory")
#define CP_COMMIT() asm volatile("cp.async.commit_group;" ::: "memory")
#define CP_WAIT1()  asm volatile("cp.async.wait_group 1;" ::: "memory")
#define CP_WAIT0()  asm volatile("cp.async.wait_group 0;" ::: "memory")

// -------- fp32 -> fp16 bulk convert --------
__global__ void __launch_bounds__(256) cvt_fp16_kernel(
    const float* __restrict__ s, __half* __restrict__ d, int n8)
{
    int i = blockIdx.x * blockDim.x + threadIdx.x;
    int stride = gridDim.x * blockDim.x;
    for (; i < n8; i += stride) {
        const float4* sp = (const float4*)s + 2 * (size_t)i;
        *(uint4*)((char*)d + 16 * (size_t)i) = pack8h(sp[0], sp[1]);
    }
}

__global__ void zero_prog() {
    if (threadIdx.x < Tn) g_prog[threadIdx.x] = 0;
}

// ============================================================================
// worker path: pre-GEMM tiles in t-major order (validated r8 body, remapped)
// tile tl: t = tl>>4, sub = tl&15, ntile = sub&3, bblk = sub>>2
// computes pre[t][bblk*128 .. +128][ntile*128 .. +128]
// ============================================================================
__device__ void pre_worker(char* sm, uint32_t sb,
                           const __half* __restrict__ Ah,
                           const __half* __restrict__ Wh,
                           const float* __restrict__ b1,
                           const float* __restrict__ b2,
                           float* __restrict__ pre)
{
    const int tid  = threadIdx.x;
    const int lane = tid & 31;
    const int wid  = tid >> 5;
    const int widx = blockIdx.x - NRCTA;
    float* bias_s = (float*)(sm + 49152);

    const int r   = tid >> 1;
    const int u0  = (tid & 1) * 2;
    const int ssw = (r >> 1) & 3;
    const uint32_t so0 = r * 64 + (((u0)     ^ ssw) << 4);
    const uint32_t so1 = r * 64 + (((u0 + 1) ^ ssw) << 4);

    const int m0w = (wid >> 1) * 32;
    const int n0w = (wid & 1) * 64;

    const int rowA = m0w + (lane & 15);
    const int jA   = lane >> 4;
    const int swA  = (rowA >> 1) & 3;
    const uint32_t aA = sb + rowA * 64;
    const int rowB = n0w + (lane & 7) + ((lane >> 4) & 1) * 8;
    const int jB   = (lane >> 3) & 1;
    const int swB  = (rowB >> 1) & 3;
    const uint32_t aB = sb + 8192 + rowB * 64;

#pragma unroll 1
    for (int tl = widx; tl < NTILE; tl += NWORK) {
        const int t    = tl >> 4;
        const int sub  = tl & 15;
        const int n0   = (sub & 3) * 128;
        const int bk   = (sub >> 2) * 128;

        const __half* arow = Ah + (size_t)(bk + r) * (Tn * Dn) + (size_t)t * Dn;
        const __half* brow = Wh + (size_t)(n0 + r) * Dn;
        if (tid < 128) bias_s[tid] = b1[n0 + tid] + b2[n0 + tid];

        float acc[2][8][4];
#pragma unroll
        for (int mi = 0; mi < 2; mi++)
#pragma unroll
            for (int ni = 0; ni < 8; ni++)
#pragma unroll
                for (int q = 0; q < 4; q++) acc[mi][ni][q] = 0.f;

#define W_ISSUE(kc_, stg_) do {                                     \
            const uint32_t d_ = sb + (stg_) * 16384;                \
            const __half* as_ = arow + (kc_) * 32 + u0 * 8;         \
            const __half* bs_ = brow + (kc_) * 32 + u0 * 8;         \
            CP16(d_ + so0,        as_);                             \
            CP16(d_ + so1,        as_ + 8);                         \
            CP16(d_ + 8192 + so0, bs_);                             \
            CP16(d_ + 8192 + so1, bs_ + 8);                         \
            CP_COMMIT(); } while (0)

        W_ISSUE(0, 0);
        W_ISSUE(1, 1);

#pragma unroll 1
        for (int kc = 0; kc < 32; kc++) {
            if (kc == 31) { CP_WAIT0(); } else { CP_WAIT1(); }
            __syncthreads();

            if (kc < 30) W_ISSUE(kc + 2, (kc + 2) % 3);

            const uint32_t ba  = aA + (kc % 3) * 16384;
            const uint32_t bbb = aB + (kc % 3) * 16384;
#pragma unroll
            for (int kf = 0; kf < 2; kf++) {
                uint32_t Af[2][4], Bf[4][4];
                const int ja = (((2 * kf + jA) ^ swA) << 4);
                const int jb = (((2 * kf + jB) ^ swB) << 4);
                ldsm4(Af[0], ba + ja);
                ldsm4(Af[1], ba + 1024 + ja);
#pragma unroll
                for (int ng = 0; ng < 4; ng++)
                    ldsm4(Bf[ng], bbb + ng * 1024 + jb);
#pragma unroll
                for (int mi = 0; mi < 2; mi++)
#pragma unroll
                    for (int ni = 0; ni < 8; ni++)
                        mma16816h(acc[mi][ni], Af[mi], &Bf[ni >> 1][(ni & 1) * 2]);
            }
            __syncthreads();
        }
#undef W_ISSUE

        // epilogue: pre[t][bk + rowl][n0 + nl]
#pragma unroll
        for (int mi = 0; mi < 2; mi++) {
            int rla = m0w + mi * 16 + (lane >> 2);
            float* rowa = pre + ((size_t)t * Bn + bk + rla) * G4 + n0;
            float* rowb = pre + ((size_t)t * Bn + bk + rla + 8) * G4 + n0;
#pragma unroll
            for (int ni = 0; ni < 8; ni++) {
                int nl = n0w + ni * 8 + (lane & 3) * 2;
                float bv0 = bias_s[nl], bv1 = bias_s[nl + 1];
                float2 v;
                v.x = acc[mi][ni][0] + bv0;
                v.y = acc[mi][ni][1] + bv1;
                *(float2*)(rowa + nl) = v;
                v.x = acc[mi][ni][2] + bv0;
                v.y = acc[mi][ni][3] + bv1;
                *(float2*)(rowb + nl) = v;
            }
        }

        __threadfence();
        __syncthreads();
        if (tid == 0) atomicAdd(&g_prog[t], 1u);
    }
}

// ============================================================================
// recurrence path (r16 body, pre loads gated on g_prog)
// ============================================================================
__device__ __forceinline__ float sigf(float x) {
    return __fdividef(1.f, 1.f + __expf(-x));
}
__device__ __forceinline__ float tanhfast(float x) {
    return __fmaf_rn(2.f, __fdividef(1.f, 1.f + __expf(-2.f * x)), -1.f);
}

__device__ __forceinline__ void group_barrier(int grp) {
    __syncthreads();
    if (threadIdx.x == 0) {
        const int s = grp * 32;
        __threadfence();
        unsigned gen = *(volatile unsigned*)&g_ggen[s];
        unsigned ticket = atomicAdd(&g_gcnt[s], 1);
        if (ticket == 7) {
            *(volatile unsigned*)&g_gcnt[s] = 0;
            __threadfence();
            atomicAdd(&g_ggen[s], 1);
        } else {
            while (*(volatile unsigned*)&g_ggen[s] == gen) { __nanosleep(20); }
            __threadfence();
        }
    }
    __syncthreads();
}

// SMEM byte offsets (recurrence)
#define ROF_W1   0
#define ROF_WI2  16384
#define ROF_WH2  32768
#define ROF_HA   49152
#define ROF_HB   57344
#define ROF_G    65536
#define ROF_PRE  74240
#define ROF_C1   90624
#define ROF_C2   92672
#define ROF_B2   94720
#define R_SMEM   95040

#define GS 68   // G row stride (floats)

__global__ void __launch_bounds__(256, 2) lstm_fused(
    float* __restrict__ pre,          // g_pre scratch
    const __half* __restrict__ Ah,
    const __half* __restrict__ Whf,   // Wih1 fp16
    const float* __restrict__ bih1,
    const float* __restrict__ bhh1,
    const float* __restrict__ Whh1,
    const float* __restrict__ Wih2,
    const float* __restrict__ Whh2,
    const float* __restrict__ bih2,
    const float* __restrict__ bhh2,
    float* __restrict__ h2out)
{
    extern __shared__ char sm[];
    const uint32_t sb = smem_u32(sm);

    if (blockIdx.x >= NRCTA) {
        pre_worker(sm, sb, Ah, Whf, bih1, bhh1, pre);
        return;
    }

    const int tid  = threadIdx.x;
    const int lane = tid & 31;
    const int wid  = tid >> 5;
    const int bb   = blockIdx.x >> 3;
    const int ub   = blockIdx.x & 7;

    float* Gf  = (float*)(sm + ROF_G);
    float* prs = (float*)(sm + ROF_PRE);
    float* c1s = (float*)(sm + ROF_C1);
    float* c2s = (float*)(sm + ROF_C2);
    float* b2s = (float*)(sm + ROF_B2);

    // ---- init: weights -> fp16 smem (swizzled), zero state ----
    for (int idx = tid; idx < 64 * 128; idx += 256) {
        int j = idx >> 7;
        int k = idx & 127;
        int gcol = ((j >> 4) << 7) + (ub << 4) + (j & 15);
        uint32_t ad = (uint32_t)(j * 256 + (((k >> 3) ^ (j & 7)) << 4) + (k & 7) * 2);
        *(__half*)(sm + ROF_W1  + ad) = __float2half(Whh1[(size_t)gcol * Hn + k]);
        *(__half*)(sm + ROF_WI2 + ad) = __float2half(Wih2[(size_t)gcol * Hn + k]);
        *(__half*)(sm + ROF_WH2 + ad) = __float2half(Whh2[(size_t)gcol * Hn + k]);
    }
    if (tid < 64) {
        int gcol = ((tid >> 4) << 7) + (ub << 4) + (tid & 15);
        b2s[tid] = bih2[gcol] + bhh2[gcol];
    }
    for (int i = tid; i < 512; i += 256) { c1s[i] = 0.f; c2s[i] = 0.f; }
    for (int i = tid; i < 2048; i += 256) ((uint32_t*)(sm + ROF_HA))[i] = 0;
    {
        int u = tid & 15;
        int bl = tid >> 4;
#pragma unroll
        for (int i = 0; i < 2; i++) {
            int row = bb * 32 + bl + i * 16;
            g_h1h[row * Hn + ub * 16 + u] = __float2half(0.f);
            g_h2h[row * Hn + ub * 16 + u] = __float2half(0.f);
        }
    }
    // gated prefetch of pre[0] slice into pres buf 0
    {
        while (ld_acq(&g_prog[0]) < 16u) { __nanosleep(128); }
#pragma unroll
        for (int i = 0; i < 2; i++) {
            int q = 2 * tid + i;
            int b = q >> 4, ch = q & 15;
            int gcol0 = ((ch >> 2) << 7) + (ub << 4) + (ch & 3) * 4;
            const float* src = pre + ((size_t)(bb * 32 + b)) * G4 + gcol0;
            CP16(sb + ROF_PRE + (b * 64 + ch * 4) * 4, src);
        }
        CP_COMMIT();
    }
    group_barrier(bb);

    // ---- per-thread mma geometry (warp tile 16m x 16n; 2x4 warp grid) ----
    const int m_off = (wid >> 2) * 16;
    const int n_off = (wid & 3) * 16;
    const int rowA = m_off + (lane & 15);
    const uint32_t aoffA = rowA * 256;
    const int swA = rowA & 7;
    const int kuA0 = lane >> 4;
    const int rowB = n_off + (lane & 7) + ((lane >> 4) & 1) * 8;
    const uint32_t boffB = rowB * 256;
    const int swB = rowB & 7;
    const int kuB0 = (lane >> 3) & 1;

    const int u2 = tid & 15;
    const int bq = (tid >> 4) * 2;

    auto gemm_acc = [&](uint32_t hbase, uint32_t wbase, float acc[2][4]) {
#pragma unroll
        for (int ks = 0; ks < 8; ks++) {
            uint32_t Af[4], Bf[4];
            int kuA = 2 * ks + kuA0;
            int kuB = 2 * ks + kuB0;
            ldsm4(Af, sb + hbase + aoffA + (uint32_t)(((kuA ^ swA)) << 4));
            ldsm4(Bf, sb + wbase + boffB + (uint32_t)(((kuB ^ swB)) << 4));
            mma16816h(acc[0], Af, Bf);
            mma16816h(acc[1], Af, Bf + 2);
        }
    };
    auto gemm2_acc = [&](uint32_t h1b, uint32_t w1b, uint32_t h2b, uint32_t w2b,
                         float acc[2][4]) {
#pragma unroll
        for (int ks = 0; ks < 8; ks++) {
            uint32_t Af[4], Bf[4], Cf[4], Df[4];
            int kuA = 2 * ks + kuA0;
            int kuB = 2 * ks + kuB0;
            uint32_t oA = (uint32_t)(((kuA ^ swA)) << 4);
            uint32_t oB = (uint32_t)(((kuB ^ swB)) << 4);
            ldsm4(Af, sb + h1b + aoffA + oA);
            ldsm4(Bf, sb + w1b + boffB + oB);
            ldsm4(Cf, sb + h2b + aoffA + oA);
            ldsm4(Df, sb + w2b + boffB + oB);
            mma16816h(acc[0], Af, Bf);
            mma16816h(acc[1], Af, Bf + 2);
            mma16816h(acc[0], Cf, Df);
            mma16816h(acc[1], Cf, Df + 2);
        }
    };
    auto stage_G = [&](float acc[2][4]) {
        int r0 = m_off + (lane >> 2);
        int c0 = n_off + 2 * (lane & 3);
#pragma unroll
        for (int h = 0; h < 2; h++) {
            Gf[r0 * GS + c0 + 8 * h]           = acc[h][0];
            Gf[r0 * GS + c0 + 8 * h + 1]       = acc[h][1];
            Gf[(r0 + 8) * GS + c0 + 8 * h]     = acc[h][2];
            Gf[(r0 + 8) * GS + c0 + 8 * h + 1] = acc[h][3];
        }
    };

#pragma unroll 1
    for (int t = 0; t < Tn; t++) {
        const int p = t & 1;
        const __half* h2cur = g_h2h + p * BH;
        __half* h1nxt = g_h1h + (1 - p) * BH;
        __half* h2nxt = g_h2h + (1 - p) * BH;
        float* presc = prs + p * 2048;

        // ===== Phase A: layer-1 gates = hA @ W1^T (+ pre) =====
        {
            float acc[2][4];
#pragma unroll
            for (int q = 0; q < 2; q++)
#pragma unroll
                for (int w = 0; w < 4; w++) acc[q][w] = 0.f;
            gemm_acc(ROF_HA, ROF_W1, acc);
            stage_G(acc);
        }
        CP_WAIT0();        // pre[t] landed
        __syncthreads();
#pragma unroll
        for (int i = 0; i < 2; i++) {
            int b = bq + i;
            float iv = Gf[b * GS + u2]      + presc[b * 64 + u2];
            float fv = Gf[b * GS + 16 + u2] + presc[b * 64 + 16 + u2];
            float gv = Gf[b * GS + 32 + u2] + presc[b * 64 + 32 + u2];
            float ov = Gf[b * GS + 48 + u2] + presc[b * 64 + 48 + u2];
            int ci = b * 16 + u2;
            float cp = c1s[ci];
            float cn = sigf(fv) * cp + sigf(iv) * tanhfast(gv);
            c1s[ci] = cn;
            h1nxt[(bb * 32 + b) * Hn + ub * 16 + u2] = __float2half(sigf(ov) * tanhfast(cn));
        }
        group_barrier(bb);

        // ===== Phase B: layer-2 gates = h1new @ Wi2^T + h2 @ Wh2^T + b2 =====
        {
#pragma unroll
            for (int i = 0; i < 2; i++) {
                int q = 2 * tid + i;
                int rr = q >> 4, ku = q & 15;
                uint32_t doff = (uint32_t)(rr * 256 + ((ku ^ (rr & 7)) << 4));
                CP16(sb + ROF_HA + doff, h1nxt + (bb * 32 + rr) * Hn + ku * 8);
                CP16(sb + ROF_HB + doff, h2cur + (bb * 32 + rr) * Hn + ku * 8);
            }
            CP_COMMIT();
        }
        if (t < Tn - 1) {
            // gate on producer, then prefetch pre[t+1]
            while (ld_acq(&g_prog[t + 1]) < 16u) { __nanosleep(128); }
#pragma unroll
            for (int i = 0; i < 2; i++) {
                int q = 2 * tid + i;
                int b = q >> 4, ch = q & 15;
                int gcol0 = ((ch >> 2) << 7) + (ub << 4) + (ch & 3) * 4;
                const float* src = pre + ((size_t)(t + 1) * Bn + bb * 32 + b) * G4 + gcol0;
                CP16(sb + ROF_PRE + (((t + 1) & 1) * 2048 + b * 64 + ch * 4) * 4, src);
            }
            CP_COMMIT();
            CP_WAIT1();
        } else {
            CP_WAIT0();
        }
        __syncthreads();
        {
            float acc[2][4];
#pragma unroll
            for (int q = 0; q < 2; q++)
#pragma unroll
                for (int w = 0; w < 4; w++) acc[q][w] = 0.f;
            gemm2_acc(ROF_HA, ROF_WI2, ROF_HB, ROF_WH2, acc);
            stage_G(acc);
        }
        __syncthreads();
#pragma unroll
        for (int i = 0; i < 2; i++) {
            int b = bq + i;
            float iv = Gf[b * GS + u2]      + b2s[u2];
            float fv = Gf[b * GS + 16 + u2] + b2s[16 + u2];
            float gv = Gf[b * GS + 32 + u2] + b2s[32 + u2];
            float ov = Gf[b * GS + 48 + u2] + b2s[48 + u2];
            int ci = b * 16 + u2;
            float cp = c2s[ci];
            float cn = sigf(fv) * cp + sigf(iv) * tanhfast(gv);
            c2s[ci] = cn;
            float hn = sigf(ov) * tanhfast(cn);
            h2nxt[(bb * 32 + b) * Hn + ub * 16 + u2] = __float2half(hn);
            if (t == Tn - 1)
                h2out[(bb * 32 + b) * Hn + ub * 16 + u2] = hn;
        }
        __syncthreads();
    }
}

// -------- launch --------
extern "C" void kernel_launch(void* const* d_in, const int* in_sizes, int n_in,
                              void* d_out, int out_size) {
    const float* feats = (const float*)d_in[0];
    const float* Wih1  = (const float*)d_in[1];
    const float* Whh1  = (const float*)d_in[2];
    const float* bih1  = (const float*)d_in[3];
    const float* bhh1  = (const float*)d_in[4];
    const float* Wih2  = (const float*)d_in[5];
    const float* Whh2  = (const float*)d_in[6];
    const float* bih2  = (const float*)d_in[7];
    const float* bhh2  = (const float*)d_in[8];

    float* pre;
    __half *Ah, *Wh;
    cudaGetSymbolAddress((void**)&pre, g_pre);
    cudaGetSymbolAddress((void**)&Ah,  g_Ah);
    cudaGetSymbolAddress((void**)&Wh,  g_Wh);

    static int attr_set = 0;
    if (!attr_set) {
        cudaFuncSetAttribute(lstm_fused,
                             cudaFuncAttributeMaxDynamicSharedMemorySize,
                             R_SMEM);
        attr_set = 1;
    }

    // fp32 -> fp16 staging
    cvt_fp16_kernel<<<4096, 256>>>(feats, Ah, (Bn * Tn * Dn) / 8);
    cvt_fp16_kernel<<<256, 256>>>(Wih1, Wh, (G4 * Dn) / 8);
    zero_prog<<<1, 128>>>();

    // fused producer (148 GEMM workers) + consumer (128 recurrence CTAs)
    lstm_fused<<<NRCTA + NWORK, 256, R_SMEM>>>(
        pre, Ah, Wh, bih1, bhh1, Whh1, Wih2, Whh2, bih2, bhh2,
        (float*)d_out);
}